// round 13
// baseline (speedup 1.0000x reference)
#include <cuda_runtime.h>
#include <cuda_fp16.h>
#include <cstdint>

#define BATCH 4
#define SEQ   2048
#define DIN   2048
#define DOUT  2048
#define MTOT  (BATCH * SEQ)   // 8192 tokens
#define GROUP 32
#define NGROUP (DIN / GROUP)  // 64

// GEMM tiling: 128x128 CTA tile, BK=64 halves, 3 stages (R11-proven)
#define BM 128
#define BN 128
#define BK 64                 // halves per K-chunk
#define STAGES 3
#define NKT (DIN / BK)        // 32
#define PITCH 72              // halves per smem row (144B, conflict-free ldmatrix)
#define ROWB (PITCH * 2)      // 144 bytes
#define A_BYTES (BM * ROWB)           // 18432
#define STAGE_B (2 * A_BYTES)         // 36864
#define SMEM_TOTAL (STAGES * STAGE_B) // 110592

// prep kernel partition
#define QBLOCKS (MTOT / 8)             // 1024 blocks x 8 warps = 1 token/warp
#define WBLOCKS (DOUT * DIN / 4 / 256) // 4096

// Scratch (allocation-free rule: __device__ globals)
__device__ __half g_A[(size_t)MTOT * DIN];   // exact integer (q - zp) per token
__device__ __half g_W[(size_t)DOUT * DIN];   // dequantized weights
__device__ float  g_sx[MTOT];                // per-token activation scale

// ---------------------------------------------------------------------------
__device__ __forceinline__ void cp_async16(uint32_t saddr, const void* gaddr) {
    asm volatile("cp.async.cg.shared.global [%0], [%1], 16;\n" :: "r"(saddr), "l"(gaddr));
}
__device__ __forceinline__ void cp_commit() { asm volatile("cp.async.commit_group;\n" ::: "memory"); }
template <int N>
__device__ __forceinline__ void cp_wait() { asm volatile("cp.async.wait_group %0;\n" :: "n"(N) : "memory"); }

// ---------------------------------------------------------------------------
// Kernel 1 (fused prep): R10-proven.
//  blocks [0, QBLOCKS): warp-per-token int8 fake-quant of x (shuffle-only).
//  blocks [QBLOCKS, ...): int4 grouped weight dequant -> fp16.
// ---------------------------------------------------------------------------
__global__ void prep_kernel(const float4* __restrict__ x,
                            const int4* __restrict__ w_int,
                            const float* __restrict__ ws,
                            const float* __restrict__ wz) {
    const int bid = blockIdx.x;
    if (bid < QBLOCKS) {
        const int lane  = threadIdx.x & 31;
        const int token = bid * 8 + (threadIdx.x >> 5);
        const float4* xr = x + (size_t)token * (DIN / 4);

        float4 v[16];
        float vmin = 0.0f, vmax = 0.0f;   // reference clamps min<=0, max>=0
#pragma unroll
        for (int i = 0; i < 16; i++) {
            v[i] = xr[lane + 32 * i];
            vmin = fminf(vmin, fminf(fminf(v[i].x, v[i].y), fminf(v[i].z, v[i].w)));
            vmax = fmaxf(vmax, fmaxf(fmaxf(v[i].x, v[i].y), fmaxf(v[i].z, v[i].w)));
        }
#pragma unroll
        for (int off = 16; off > 0; off >>= 1) {
            vmin = fminf(vmin, __shfl_xor_sync(0xffffffffu, vmin, off));
            vmax = fmaxf(vmax, __shfl_xor_sync(0xffffffffu, vmax, off));
        }

        float scale = (vmax - vmin) / 255.0f;
        scale = fmaxf(scale, 1.1920928955078125e-07f);  // jnp.finfo(f32).eps
        const float inv = 1.0f / scale;
        const float zp = fminf(fmaxf(-128.0f - rintf(vmin * inv), -128.0f), 127.0f);
        if (lane == 0) g_sx[token] = scale;

        uint2* ar = (uint2*)(g_A + (size_t)token * DIN);
#define QV(f) (fminf(fmaxf(rintf((f) * inv) + zp, -128.0f), 127.0f) - zp)
#pragma unroll
        for (int i = 0; i < 16; i++) {
            __half2 h0 = __floats2half2_rn(QV(v[i].x), QV(v[i].y));
            __half2 h1 = __floats2half2_rn(QV(v[i].z), QV(v[i].w));
            uint2 p;
            p.x = *(const uint32_t*)&h0;
            p.y = *(const uint32_t*)&h1;
            ar[lane + 32 * i] = p;
        }
#undef QV
    } else {
        const int idx = (bid - QBLOCKS) * 256 + threadIdx.x;  // over DOUT*DIN/4
        int4 w = w_int[idx];
        const int k4 = idx & (DIN / 4 - 1);
        const int o  = idx / (DIN / 4);
        const int g  = (k4 * 4) / GROUP;
        const float s = ws[o * NGROUP + g];
        const float z = wz[o * NGROUP + g];
        __half2 lo = __floats2half2_rn(((float)w.x - z) * s, ((float)w.y - z) * s);
        __half2 hi = __floats2half2_rn(((float)w.z - z) * s, ((float)w.w - z) * s);
        __half2* dst = (__half2*)g_W + (size_t)idx * 2;
        dst[0] = lo;
        dst[1] = hi;
    }
}

// ---------------------------------------------------------------------------
// Kernel 2: GEMM  out[m,n] = s_x[m] * sum_k A[m,k] * W[n,k]
// 128x128 CTA tile, 8 warps (2x4), warp tile 64x32, BK=64 (4 ks sub-steps),
// 3-stage cp.async wait_group 1, register double-buffered fragments:
// ldmatrix for ks+1 issued BEFORE the 16 mmas of ks (hides LDSM latency).
// ---------------------------------------------------------------------------
extern __shared__ char dsmem[];

__global__ void gemm_kernel(float* __restrict__ out) {
    const int tid  = threadIdx.x;      // 256
    const int lane = tid & 31;
    const int wid  = tid >> 5;
    const int warp_m = wid >> 2;       // 0..1  -> 64 rows
    const int warp_n = wid & 3;        // 0..3  -> 32 cols
    const int bn = blockIdx.x, bm = blockIdx.y;

    const __half* Ag = g_A + (size_t)(bm * BM) * DIN;
    const __half* Wg = g_W + (size_t)(bn * BN) * DIN;

    const uint32_t sb = (uint32_t)__cvta_generic_to_shared(dsmem);

    // cp.async chunk mapping: 1024 chunks per operand, 4+4 per thread
    const int crow = tid >> 3;           // base row 0..31 band
    const int ccb  = (tid & 7) * 16;     // chunk col in bytes

    auto load_stage = [&](int s, int kt) {
        const uint32_t aBase = sb + s * STAGE_B;
        const uint32_t bBase = aBase + A_BYTES;
        const int kh = kt * BK;          // half offset in K
        const int ch = ccb / 2;          // halves
#pragma unroll
        for (int j = 0; j < 4; j++) {
            const int r = crow + j * 32;
            cp_async16(aBase + (uint32_t)(r * ROWB + ccb), Ag + (size_t)r * DIN + kh + ch);
            cp_async16(bBase + (uint32_t)(r * ROWB + ccb), Wg + (size_t)r * DIN + kh + ch);
        }
        cp_commit();
    };

    float acc[4][4][4];
#pragma unroll
    for (int i = 0; i < 4; i++)
#pragma unroll
        for (int j = 0; j < 4; j++)
#pragma unroll
            for (int r = 0; r < 4; r++) acc[i][j][r] = 0.0f;

    // ldmatrix per-lane offsets (rows; byte col offsets)
    const int a_row  = warp_m * 64 + (lane & 15);
    const int a_colb = (lane >> 4) * 16;
    const int b_row  = warp_n * 32 + (lane & 7) + ((lane >> 4) & 1) * 8;
    const int b_colb = ((lane >> 3) & 1) * 16;

    // double-buffered fragments
    uint32_t af[2][4][4];
    uint32_t bf[2][4][2];

    auto ld_frags = [&](int buf, uint32_t aBase, uint32_t bBase, int ks) {
#pragma unroll
        for (int mt = 0; mt < 4; mt++) {
            uint32_t addr = aBase +
                (uint32_t)((a_row + mt * 16) * ROWB + ks * 32 + a_colb);
            asm volatile(
                "ldmatrix.sync.aligned.m8n8.x4.shared.b16 {%0,%1,%2,%3}, [%4];"
                : "=r"(af[buf][mt][0]), "=r"(af[buf][mt][1]),
                  "=r"(af[buf][mt][2]), "=r"(af[buf][mt][3])
                : "r"(addr));
        }
#pragma unroll
        for (int p = 0; p < 2; p++) {
            uint32_t addr = bBase +
                (uint32_t)((b_row + p * 16) * ROWB + ks * 32 + b_colb);
            uint32_t r0, r1, r2, r3;
            asm volatile(
                "ldmatrix.sync.aligned.m8n8.x4.shared.b16 {%0,%1,%2,%3}, [%4];"
                : "=r"(r0), "=r"(r1), "=r"(r2), "=r"(r3)
                : "r"(addr));
            bf[buf][2 * p][0] = r0; bf[buf][2 * p][1] = r1;
            bf[buf][2 * p + 1][0] = r2; bf[buf][2 * p + 1][1] = r3;
        }
    };

    auto do_mma = [&](int buf) {
#pragma unroll
        for (int mt = 0; mt < 4; mt++)
#pragma unroll
            for (int nt = 0; nt < 4; nt++)
                asm volatile(
                    "mma.sync.aligned.m16n8k16.row.col.f32.f16.f16.f32 "
                    "{%0,%1,%2,%3}, {%4,%5,%6,%7}, {%8,%9}, {%0,%1,%2,%3};"
                    : "+f"(acc[mt][nt][0]), "+f"(acc[mt][nt][1]),
                      "+f"(acc[mt][nt][2]), "+f"(acc[mt][nt][3])
                    : "r"(af[buf][mt][0]), "r"(af[buf][mt][1]),
                      "r"(af[buf][mt][2]), "r"(af[buf][mt][3]),
                      "r"(bf[buf][nt][0]), "r"(bf[buf][nt][1]));
    };

    load_stage(0, 0);
    load_stage(1, 1);

    int s_cur = 0, s_nxt = 2;   // rotating stage indices
#pragma unroll 1
    for (int kt = 0; kt < NKT; kt++) {
        if (kt + 1 < NKT) cp_wait<1>(); else cp_wait<0>();
        __syncthreads();
        if (kt + 2 < NKT) load_stage(s_nxt, kt + 2);

        const uint32_t aBase = sb + s_cur * STAGE_B;
        const uint32_t bBase = aBase + A_BYTES;
        s_nxt = s_cur;
        s_cur = (s_cur == 2) ? 0 : s_cur + 1;

        ld_frags(0, aBase, bBase, 0);
#pragma unroll
        for (int ks = 0; ks < 4; ks++) {
            if (ks < 3) ld_frags((ks + 1) & 1, aBase, bBase, ks + 1);
            do_mma(ks & 1);
        }
    }

    // Epilogue: scale rows by s_x and store fp32
    const int gm0 = bm * BM + warp_m * 64 + (lane >> 2);
    const int gn0 = bn * BN + warp_n * 32 + (lane & 3) * 2;
#pragma unroll
    for (int mt = 0; mt < 4; mt++) {
        const int r0 = gm0 + mt * 16;
        const float s0 = g_sx[r0];
        const float s1 = g_sx[r0 + 8];
#pragma unroll
        for (int nt = 0; nt < 4; nt++) {
            const int c = gn0 + nt * 8;
            float2 v0 = make_float2(acc[mt][nt][0] * s0, acc[mt][nt][1] * s0);
            float2 v1 = make_float2(acc[mt][nt][2] * s1, acc[mt][nt][3] * s1);
            *(float2*)&out[(size_t)r0 * DOUT + c] = v0;
            *(float2*)&out[(size_t)(r0 + 8) * DOUT + c] = v1;
        }
    }
}

// ---------------------------------------------------------------------------
extern "C" void kernel_launch(void* const* d_in, const int* in_sizes, int n_in,
                              void* d_out, int out_size) {
    (void)in_sizes; (void)n_in; (void)out_size;
    const float* x      = (const float*)d_in[0];
    const int*   w_int  = (const int*)d_in[1];
    const float* w_sc   = (const float*)d_in[2];
    const float* w_zp   = (const float*)d_in[3];
    float* out = (float*)d_out;

    cudaFuncSetAttribute(gemm_kernel, cudaFuncAttributeMaxDynamicSharedMemorySize, SMEM_TOTAL);

    prep_kernel<<<QBLOCKS + WBLOCKS, 256>>>((const float4*)x, (const int4*)w_int, w_sc, w_zp);
    gemm_kernel<<<dim3(DOUT / BN, MTOT / BM), 256, SMEM_TOTAL>>>(out);
}

// round 15
// speedup vs baseline: 1.0870x; 1.0870x over previous
#include <cuda_runtime.h>
#include <cuda_fp16.h>
#include <cstdint>

#define BATCH 4
#define SEQ   2048
#define DIN   2048
#define DOUT  2048
#define MTOT  (BATCH * SEQ)   // 8192 tokens
#define GROUP 32
#define NGROUP (DIN / GROUP)  // 64

// GEMM tiling: 128x128 CTA tile, BK=64 halves, 3 stages (R11-proven)
#define BM 128
#define BN 128
#define BK 64                 // halves per K-chunk
#define STAGES 3
#define NKT (DIN / BK)        // 32
#define PITCH 72              // halves per smem row (144B, conflict-free ldmatrix)
#define ROWB (PITCH * 2)      // 144 bytes
#define A_BYTES (BM * ROWB)           // 18432
#define STAGE_B (2 * A_BYTES)         // 36864
#define SMEM_TOTAL (STAGES * STAGE_B) // 110592

// prep kernel partition
#define QBLOCKS (MTOT / 8)             // 1024 blocks x 8 warps = 1 token/warp
#define WBLOCKS (DOUT * DIN / 4 / 256) // 4096

// Scratch (allocation-free rule: __device__ globals)
__device__ __half g_A[(size_t)MTOT * DIN];   // exact integer (q - zp) per token
__device__ __half g_W[(size_t)DOUT * DIN];   // dequantized weights
__device__ float  g_sx[MTOT];                // per-token activation scale

// ---------------------------------------------------------------------------
__device__ __forceinline__ void cp_async16(uint32_t saddr, const void* gaddr) {
    asm volatile("cp.async.cg.shared.global [%0], [%1], 16;\n" :: "r"(saddr), "l"(gaddr));
}
__device__ __forceinline__ void cp_commit() { asm volatile("cp.async.commit_group;\n" ::: "memory"); }
template <int N>
__device__ __forceinline__ void cp_wait() { asm volatile("cp.async.wait_group %0;\n" :: "n"(N) : "memory"); }

#define LDSM4(d0, d1, d2, d3, addr) \
    asm volatile("ldmatrix.sync.aligned.m8n8.x4.shared.b16 {%0,%1,%2,%3}, [%4];" \
                 : "=r"(d0), "=r"(d1), "=r"(d2), "=r"(d3) : "r"(addr))

#define MMA16816(acc, a, b) \
    asm volatile("mma.sync.aligned.m16n8k16.row.col.f32.f16.f16.f32 " \
                 "{%0,%1,%2,%3}, {%4,%5,%6,%7}, {%8,%9}, {%0,%1,%2,%3};" \
                 : "+f"((acc)[0]), "+f"((acc)[1]), "+f"((acc)[2]), "+f"((acc)[3]) \
                 : "r"((a)[0]), "r"((a)[1]), "r"((a)[2]), "r"((a)[3]), \
                   "r"((b)[0]), "r"((b)[1]))

// ---------------------------------------------------------------------------
// Kernel 1 (fused prep): R10-proven.
//  blocks [0, QBLOCKS): warp-per-token int8 fake-quant of x (shuffle-only).
//  blocks [QBLOCKS, ...): int4 grouped weight dequant -> fp16.
// ---------------------------------------------------------------------------
__global__ void prep_kernel(const float4* __restrict__ x,
                            const int4* __restrict__ w_int,
                            const float* __restrict__ ws,
                            const float* __restrict__ wz) {
    const int bid = blockIdx.x;
    if (bid < QBLOCKS) {
        const int lane  = threadIdx.x & 31;
        const int token = bid * 8 + (threadIdx.x >> 5);
        const float4* xr = x + (size_t)token * (DIN / 4);

        float4 v[16];
        float vmin = 0.0f, vmax = 0.0f;   // reference clamps min<=0, max>=0
#pragma unroll
        for (int i = 0; i < 16; i++) {
            v[i] = xr[lane + 32 * i];
            vmin = fminf(vmin, fminf(fminf(v[i].x, v[i].y), fminf(v[i].z, v[i].w)));
            vmax = fmaxf(vmax, fmaxf(fmaxf(v[i].x, v[i].y), fmaxf(v[i].z, v[i].w)));
        }
#pragma unroll
        for (int off = 16; off > 0; off >>= 1) {
            vmin = fminf(vmin, __shfl_xor_sync(0xffffffffu, vmin, off));
            vmax = fmaxf(vmax, __shfl_xor_sync(0xffffffffu, vmax, off));
        }

        float scale = (vmax - vmin) / 255.0f;
        scale = fmaxf(scale, 1.1920928955078125e-07f);  // jnp.finfo(f32).eps
        const float inv = 1.0f / scale;
        const float zp = fminf(fmaxf(-128.0f - rintf(vmin * inv), -128.0f), 127.0f);
        if (lane == 0) g_sx[token] = scale;

        uint2* ar = (uint2*)(g_A + (size_t)token * DIN);
#define QV(f) (fminf(fmaxf(rintf((f) * inv) + zp, -128.0f), 127.0f) - zp)
#pragma unroll
        for (int i = 0; i < 16; i++) {
            __half2 h0 = __floats2half2_rn(QV(v[i].x), QV(v[i].y));
            __half2 h1 = __floats2half2_rn(QV(v[i].z), QV(v[i].w));
            uint2 p;
            p.x = *(const uint32_t*)&h0;
            p.y = *(const uint32_t*)&h1;
            ar[lane + 32 * i] = p;
        }
#undef QV
    } else {
        const int idx = (bid - QBLOCKS) * 256 + threadIdx.x;  // over DOUT*DIN/4
        int4 w = w_int[idx];
        const int k4 = idx & (DIN / 4 - 1);
        const int o  = idx / (DIN / 4);
        const int g  = (k4 * 4) / GROUP;
        const float s = ws[o * NGROUP + g];
        const float z = wz[o * NGROUP + g];
        __half2 lo = __floats2half2_rn(((float)w.x - z) * s, ((float)w.y - z) * s);
        __half2 hi = __floats2half2_rn(((float)w.z - z) * s, ((float)w.w - z) * s);
        __half2* dst = (__half2*)g_W + (size_t)idx * 2;
        dst[0] = lo;
        dst[1] = hi;
    }
}

// ---------------------------------------------------------------------------
// Kernel 2: GEMM  out[m,n] = s_x[m] * sum_k A[m,k] * W[n,k]
// 128x128 CTA tile, 8 warps (2x4), warp tile 64x32, BK=64 (4 ks sub-steps),
// 3-stage cp.async wait_group 1. R11 structure with ONE change: ks=0 fragment
// ldmatrix issues BEFORE the next-stage cp.async burst, so MMAs start at the
// chunk head and LDGSTS issue overlaps tensor work.
// ---------------------------------------------------------------------------
extern __shared__ char dsmem[];

__global__ void gemm_kernel(float* __restrict__ out) {
    const int tid  = threadIdx.x;      // 256
    const int lane = tid & 31;
    const int wid  = tid >> 5;
    const int warp_m = wid >> 2;       // 0..1  -> 64 rows
    const int warp_n = wid & 3;        // 0..3  -> 32 cols
    const int bn = blockIdx.x, bm = blockIdx.y;

    const __half* Ag = g_A + (size_t)(bm * BM) * DIN;
    const __half* Wg = g_W + (size_t)(bn * BN) * DIN;

    const uint32_t sb = (uint32_t)__cvta_generic_to_shared(dsmem);

    // cp.async chunk mapping: 1024 chunks per operand, 4+4 per thread
    const int crow = tid >> 3;           // base row 0..31 band
    const int ccb  = (tid & 7) * 16;     // chunk col in bytes

    auto load_stage = [&](int s, int kt) {
        const uint32_t aBase = sb + s * STAGE_B;
        const uint32_t bBase = aBase + A_BYTES;
        const int kh = kt * BK;          // half offset in K
        const int ch = ccb / 2;          // halves
#pragma unroll
        for (int j = 0; j < 4; j++) {
            const int r = crow + j * 32;
            cp_async16(aBase + (uint32_t)(r * ROWB + ccb), Ag + (size_t)r * DIN + kh + ch);
            cp_async16(bBase + (uint32_t)(r * ROWB + ccb), Wg + (size_t)r * DIN + kh + ch);
        }
        cp_commit();
    };

    float acc[4][4][4];
#pragma unroll
    for (int i = 0; i < 4; i++)
#pragma unroll
        for (int j = 0; j < 4; j++)
#pragma unroll
            for (int r = 0; r < 4; r++) acc[i][j][r] = 0.0f;

    // ldmatrix per-lane offsets (rows; byte col offsets)
    const int a_row  = warp_m * 64 + (lane & 15);
    const int a_colb = (lane >> 4) * 16;
    const int b_row  = warp_n * 32 + (lane & 7) + ((lane >> 4) & 1) * 8;
    const int b_colb = ((lane >> 3) & 1) * 16;

    load_stage(0, 0);
    load_stage(1, 1);

    int s_cur = 0, s_nxt = 2;   // rotating stage indices
#pragma unroll 1
    for (int kt = 0; kt < NKT; kt++) {
        if (kt + 1 < NKT) cp_wait<1>(); else cp_wait<0>();
        __syncthreads();

        const uint32_t aBase = sb + s_cur * STAGE_B;
        const uint32_t bBase = aBase + A_BYTES;

        // --- ks = 0: fragments FIRST (tensor pipe starts ASAP) ---
        uint32_t af[4][4];
        uint32_t bf[4][2];
#pragma unroll
        for (int mt = 0; mt < 4; mt++)
            LDSM4(af[mt][0], af[mt][1], af[mt][2], af[mt][3],
                  aBase + (uint32_t)((a_row + mt * 16) * ROWB + a_colb));
#pragma unroll
        for (int p = 0; p < 2; p++) {
            uint32_t r0, r1, r2, r3;
            LDSM4(r0, r1, r2, r3,
                  bBase + (uint32_t)((b_row + p * 16) * ROWB + b_colb));
            bf[2 * p][0] = r0; bf[2 * p][1] = r1;
            bf[2 * p + 1][0] = r2; bf[2 * p + 1][1] = r3;
        }

        // next-stage global loads issue UNDER the ks=0 MMA stream
        if (kt + 2 < NKT) load_stage(s_nxt, kt + 2);
        s_nxt = s_cur;
        s_cur = (s_cur == 2) ? 0 : s_cur + 1;

#pragma unroll
        for (int mt = 0; mt < 4; mt++)
#pragma unroll
            for (int nt = 0; nt < 4; nt++)
                MMA16816(acc[mt][nt], af[mt], bf[nt]);

        // --- ks = 1..3 (R11-proven pattern) ---
#pragma unroll
        for (int ks = 1; ks < 4; ks++) {
#pragma unroll
            for (int mt = 0; mt < 4; mt++)
                LDSM4(af[mt][0], af[mt][1], af[mt][2], af[mt][3],
                      aBase + (uint32_t)((a_row + mt * 16) * ROWB + ks * 32 + a_colb));
#pragma unroll
            for (int p = 0; p < 2; p++) {
                uint32_t r0, r1, r2, r3;
                LDSM4(r0, r1, r2, r3,
                      bBase + (uint32_t)((b_row + p * 16) * ROWB + ks * 32 + b_colb));
                bf[2 * p][0] = r0; bf[2 * p][1] = r1;
                bf[2 * p + 1][0] = r2; bf[2 * p + 1][1] = r3;
            }
#pragma unroll
            for (int mt = 0; mt < 4; mt++)
#pragma unroll
                for (int nt = 0; nt < 4; nt++)
                    MMA16816(acc[mt][nt], af[mt], bf[nt]);
        }
    }

    // Epilogue: scale rows by s_x and store fp32
    const int gm0 = bm * BM + warp_m * 64 + (lane >> 2);
    const int gn0 = bn * BN + warp_n * 32 + (lane & 3) * 2;
#pragma unroll
    for (int mt = 0; mt < 4; mt++) {
        const int r0 = gm0 + mt * 16;
        const float s0 = g_sx[r0];
        const float s1 = g_sx[r0 + 8];
#pragma unroll
        for (int nt = 0; nt < 4; nt++) {
            const int c = gn0 + nt * 8;
            float2 v0 = make_float2(acc[mt][nt][0] * s0, acc[mt][nt][1] * s0);
            float2 v1 = make_float2(acc[mt][nt][2] * s1, acc[mt][nt][3] * s1);
            *(float2*)&out[(size_t)r0 * DOUT + c] = v0;
            *(float2*)&out[(size_t)(r0 + 8) * DOUT + c] = v1;
        }
    }
}

// ---------------------------------------------------------------------------
extern "C" void kernel_launch(void* const* d_in, const int* in_sizes, int n_in,
                              void* d_out, int out_size) {
    (void)in_sizes; (void)n_in; (void)out_size;
    const float* x      = (const float*)d_in[0];
    const int*   w_int  = (const int*)d_in[1];
    const float* w_sc   = (const float*)d_in[2];
    const float* w_zp   = (const float*)d_in[3];
    float* out = (float*)d_out;

    cudaFuncSetAttribute(gemm_kernel, cudaFuncAttributeMaxDynamicSharedMemorySize, SMEM_TOTAL);

    prep_kernel<<<QBLOCKS + WBLOCKS, 256>>>((const float4*)x, (const int4*)w_int, w_sc, w_zp);
    gemm_kernel<<<dim3(DOUT / BN, MTOT / BM), 256, SMEM_TOTAL>>>(out);
}

// round 16
// speedup vs baseline: 1.1082x; 1.0195x over previous
#include <cuda_runtime.h>
#include <cuda_fp16.h>
#include <cstdint>

#define BATCH 4
#define SEQ   2048
#define DIN   2048
#define DOUT  2048
#define MTOT  (BATCH * SEQ)   // 8192 tokens
#define GROUP 32
#define NGROUP (DIN / GROUP)  // 64

// GEMM tiling: 128x128 CTA tile, BK=64 halves, 3 stages (R13-proven body)
#define BM 128
#define BN 128
#define BK 64                 // halves per K-chunk
#define STAGES 3
#define NKT (DIN / BK)        // 32
#define PITCH 72              // halves per smem row (144B, conflict-free ldmatrix)
#define ROWB (PITCH * 2)      // 144 bytes
#define A_BYTES (BM * ROWB)           // 18432
#define STAGE_B (2 * A_BYTES)         // 36864
#define SMEM_TOTAL (STAGES * STAGE_B) // 110592

#define NTILES ((MTOT / BM) * (DOUT / BN))   // 1024
#define BN_TILES (DOUT / BN)                 // 16

// prep kernel partition
#define QBLOCKS (MTOT / 8)             // 1024 blocks x 8 warps = 1 token/warp
#define WBLOCKS (DOUT * DIN / 4 / 256) // 4096

// Scratch (allocation-free rule: __device__ globals)
__device__ __half g_A[(size_t)MTOT * DIN];   // exact integer (q - zp) per token
__device__ __half g_W[(size_t)DOUT * DIN];   // dequantized weights
__device__ float  g_sx[MTOT];                // per-token activation scale
__device__ int    g_tile_cnt;                // persistent-GEMM work queue

// ---------------------------------------------------------------------------
__device__ __forceinline__ void cp_async16(uint32_t saddr, const void* gaddr) {
    asm volatile("cp.async.cg.shared.global [%0], [%1], 16;\n" :: "r"(saddr), "l"(gaddr));
}
__device__ __forceinline__ void cp_commit() { asm volatile("cp.async.commit_group;\n" ::: "memory"); }
template <int N>
__device__ __forceinline__ void cp_wait() { asm volatile("cp.async.wait_group %0;\n" :: "n"(N) : "memory"); }

#define LDSM4(d0, d1, d2, d3, addr) \
    asm volatile("ldmatrix.sync.aligned.m8n8.x4.shared.b16 {%0,%1,%2,%3}, [%4];" \
                 : "=r"(d0), "=r"(d1), "=r"(d2), "=r"(d3) : "r"(addr))

#define MMA16816(acc, a, b) \
    asm volatile("mma.sync.aligned.m16n8k16.row.col.f32.f16.f16.f32 " \
                 "{%0,%1,%2,%3}, {%4,%5,%6,%7}, {%8,%9}, {%0,%1,%2,%3};" \
                 : "+f"((acc)[0]), "+f"((acc)[1]), "+f"((acc)[2]), "+f"((acc)[3]) \
                 : "r"((a)[0]), "r"((a)[1]), "r"((a)[2]), "r"((a)[3]), \
                   "r"((b)[0]), "r"((b)[1]))

// ---------------------------------------------------------------------------
// Kernel 1 (fused prep): R10-proven.  Block 0 also resets the GEMM tile queue
// (kernel-boundary ordering makes it visible before gemm_kernel starts).
// ---------------------------------------------------------------------------
__global__ void prep_kernel(const float4* __restrict__ x,
                            const int4* __restrict__ w_int,
                            const float* __restrict__ ws,
                            const float* __restrict__ wz) {
    const int bid = blockIdx.x;
    if (bid == 0 && threadIdx.x == 0) g_tile_cnt = 0;
    if (bid < QBLOCKS) {
        const int lane  = threadIdx.x & 31;
        const int token = bid * 8 + (threadIdx.x >> 5);
        const float4* xr = x + (size_t)token * (DIN / 4);

        float4 v[16];
        float vmin = 0.0f, vmax = 0.0f;   // reference clamps min<=0, max>=0
#pragma unroll
        for (int i = 0; i < 16; i++) {
            v[i] = xr[lane + 32 * i];
            vmin = fminf(vmin, fminf(fminf(v[i].x, v[i].y), fminf(v[i].z, v[i].w)));
            vmax = fmaxf(vmax, fmaxf(fmaxf(v[i].x, v[i].y), fmaxf(v[i].z, v[i].w)));
        }
#pragma unroll
        for (int off = 16; off > 0; off >>= 1) {
            vmin = fminf(vmin, __shfl_xor_sync(0xffffffffu, vmin, off));
            vmax = fmaxf(vmax, __shfl_xor_sync(0xffffffffu, vmax, off));
        }

        float scale = (vmax - vmin) / 255.0f;
        scale = fmaxf(scale, 1.1920928955078125e-07f);  // jnp.finfo(f32).eps
        const float inv = 1.0f / scale;
        const float zp = fminf(fmaxf(-128.0f - rintf(vmin * inv), -128.0f), 127.0f);
        if (lane == 0) g_sx[token] = scale;

        uint2* ar = (uint2*)(g_A + (size_t)token * DIN);
#define QV(f) (fminf(fmaxf(rintf((f) * inv) + zp, -128.0f), 127.0f) - zp)
#pragma unroll
        for (int i = 0; i < 16; i++) {
            __half2 h0 = __floats2half2_rn(QV(v[i].x), QV(v[i].y));
            __half2 h1 = __floats2half2_rn(QV(v[i].z), QV(v[i].w));
            uint2 p;
            p.x = *(const uint32_t*)&h0;
            p.y = *(const uint32_t*)&h1;
            ar[lane + 32 * i] = p;
        }
#undef QV
    } else {
        const int idx = (bid - QBLOCKS) * 256 + threadIdx.x;  // over DOUT*DIN/4
        int4 w = w_int[idx];
        const int k4 = idx & (DIN / 4 - 1);
        const int o  = idx / (DIN / 4);
        const int g  = (k4 * 4) / GROUP;
        const float s = ws[o * NGROUP + g];
        const float z = wz[o * NGROUP + g];
        __half2 lo = __floats2half2_rn(((float)w.x - z) * s, ((float)w.y - z) * s);
        __half2 hi = __floats2half2_rn(((float)w.z - z) * s, ((float)w.w - z) * s);
        __half2* dst = (__half2*)g_W + (size_t)idx * 2;
        dst[0] = lo;
        dst[1] = hi;
    }
}

// ---------------------------------------------------------------------------
// Kernel 2: PERSISTENT GEMM.  out[m,n] = s_x[m] * sum_k A[m,k] * W[n,k]
// Each CTA loops, grabbing 128x128 tiles from a global atomic queue
// (dynamic load balancing kills the 3.46-wave quantization tail).
// Tile body = R13-proven: BK=64, 3-stage cp.async wait_group 1, ks=0 peel.
// ---------------------------------------------------------------------------
extern __shared__ char dsmem[];

__global__ void gemm_kernel(float* __restrict__ out) {
    const int tid  = threadIdx.x;      // 256
    const int lane = tid & 31;
    const int wid  = tid >> 5;
    const int warp_m = wid >> 2;       // 0..1  -> 64 rows
    const int warp_n = wid & 3;        // 0..3  -> 32 cols

    const uint32_t sb = (uint32_t)__cvta_generic_to_shared(dsmem);

    // cp.async chunk mapping: 1024 chunks per operand, 4+4 per thread
    const int crow = tid >> 3;           // base row 0..31 band
    const int ccb  = (tid & 7) * 16;     // chunk col in bytes

    // ldmatrix per-lane offsets (rows; byte col offsets)
    const int a_row  = warp_m * 64 + (lane & 15);
    const int a_colb = (lane >> 4) * 16;
    const int b_row  = warp_n * 32 + (lane & 7) + ((lane >> 4) & 1) * 8;
    const int b_colb = ((lane >> 3) & 1) * 16;

    __shared__ int s_tile;

    for (;;) {
        if (tid == 0) s_tile = atomicAdd(&g_tile_cnt, 1);
        __syncthreads();                 // also WAR barrier across tiles
        const int t = s_tile;
        if (t >= NTILES) break;
        const int bn = t & (BN_TILES - 1);
        const int bm = t >> 4;

        const __half* Ag = g_A + (size_t)(bm * BM) * DIN;
        const __half* Wg = g_W + (size_t)(bn * BN) * DIN;

        auto load_stage = [&](int s, int kt) {
            const uint32_t aBase = sb + s * STAGE_B;
            const uint32_t bBase = aBase + A_BYTES;
            const int kh = kt * BK;          // half offset in K
            const int ch = ccb / 2;          // halves
#pragma unroll
            for (int j = 0; j < 4; j++) {
                const int r = crow + j * 32;
                cp_async16(aBase + (uint32_t)(r * ROWB + ccb), Ag + (size_t)r * DIN + kh + ch);
                cp_async16(bBase + (uint32_t)(r * ROWB + ccb), Wg + (size_t)r * DIN + kh + ch);
            }
            cp_commit();
        };

        float acc[4][4][4];
#pragma unroll
        for (int i = 0; i < 4; i++)
#pragma unroll
            for (int j = 0; j < 4; j++)
#pragma unroll
                for (int r = 0; r < 4; r++) acc[i][j][r] = 0.0f;

        load_stage(0, 0);
        load_stage(1, 1);

        int s_cur = 0, s_nxt = 2;   // rotating stage indices
#pragma unroll 1
        for (int kt = 0; kt < NKT; kt++) {
            if (kt + 1 < NKT) cp_wait<1>(); else cp_wait<0>();
            __syncthreads();

            const uint32_t aBase = sb + s_cur * STAGE_B;
            const uint32_t bBase = aBase + A_BYTES;

            // --- ks = 0: fragments FIRST (tensor pipe starts ASAP) ---
            uint32_t af[4][4];
            uint32_t bf[4][2];
#pragma unroll
            for (int mt = 0; mt < 4; mt++)
                LDSM4(af[mt][0], af[mt][1], af[mt][2], af[mt][3],
                      aBase + (uint32_t)((a_row + mt * 16) * ROWB + a_colb));
#pragma unroll
            for (int p = 0; p < 2; p++) {
                uint32_t r0, r1, r2, r3;
                LDSM4(r0, r1, r2, r3,
                      bBase + (uint32_t)((b_row + p * 16) * ROWB + b_colb));
                bf[2 * p][0] = r0; bf[2 * p][1] = r1;
                bf[2 * p + 1][0] = r2; bf[2 * p + 1][1] = r3;
            }

            // next-stage global loads issue UNDER the ks=0 MMA stream
            if (kt + 2 < NKT) load_stage(s_nxt, kt + 2);
            s_nxt = s_cur;
            s_cur = (s_cur == 2) ? 0 : s_cur + 1;

#pragma unroll
            for (int mt = 0; mt < 4; mt++)
#pragma unroll
                for (int nt = 0; nt < 4; nt++)
                    MMA16816(acc[mt][nt], af[mt], bf[nt]);

            // --- ks = 1..3 ---
#pragma unroll
            for (int ks = 1; ks < 4; ks++) {
#pragma unroll
                for (int mt = 0; mt < 4; mt++)
                    LDSM4(af[mt][0], af[mt][1], af[mt][2], af[mt][3],
                          aBase + (uint32_t)((a_row + mt * 16) * ROWB + ks * 32 + a_colb));
#pragma unroll
                for (int p = 0; p < 2; p++) {
                    uint32_t r0, r1, r2, r3;
                    LDSM4(r0, r1, r2, r3,
                          bBase + (uint32_t)((b_row + p * 16) * ROWB + ks * 32 + b_colb));
                    bf[2 * p][0] = r0; bf[2 * p][1] = r1;
                    bf[2 * p + 1][0] = r2; bf[2 * p + 1][1] = r3;
                }
#pragma unroll
                for (int mt = 0; mt < 4; mt++)
#pragma unroll
                    for (int nt = 0; nt < 4; nt++)
                        MMA16816(acc[mt][nt], af[mt], bf[nt]);
            }
        }

        // Epilogue: scale rows by s_x and store fp32
        const int gm0 = bm * BM + warp_m * 64 + (lane >> 2);
        const int gn0 = bn * BN + warp_n * 32 + (lane & 3) * 2;
#pragma unroll
        for (int mt = 0; mt < 4; mt++) {
            const int r0 = gm0 + mt * 16;
            const float s0 = g_sx[r0];
            const float s1 = g_sx[r0 + 8];
#pragma unroll
            for (int nt = 0; nt < 4; nt++) {
                const int c = gn0 + nt * 8;
                float2 v0 = make_float2(acc[mt][nt][0] * s0, acc[mt][nt][1] * s0);
                float2 v1 = make_float2(acc[mt][nt][2] * s1, acc[mt][nt][3] * s1);
                *(float2*)&out[(size_t)r0 * DOUT + c] = v0;
                *(float2*)&out[(size_t)(r0 + 8) * DOUT + c] = v1;
            }
        }
    }
}

// ---------------------------------------------------------------------------
extern "C" void kernel_launch(void* const* d_in, const int* in_sizes, int n_in,
                              void* d_out, int out_size) {
    (void)in_sizes; (void)n_in; (void)out_size;
    const float* x      = (const float*)d_in[0];
    const int*   w_int  = (const int*)d_in[1];
    const float* w_sc   = (const float*)d_in[2];
    const float* w_zp   = (const float*)d_in[3];
    float* out = (float*)d_out;

    cudaFuncSetAttribute(gemm_kernel, cudaFuncAttributeMaxDynamicSharedMemorySize, SMEM_TOTAL);

    int sm_count = 148;
    cudaDeviceGetAttribute(&sm_count, cudaDevAttrMultiProcessorCount, 0);

    prep_kernel<<<QBLOCKS + WBLOCKS, 256>>>((const float4*)x, (const int4*)w_int, w_sc, w_zp);
    gemm_kernel<<<2 * sm_count, 256, SMEM_TOTAL>>>(out);
}